// round 4
// baseline (speedup 1.0000x reference)
#include <cuda_runtime.h>

// LIF, tau=2, hard reset to 0, decay_input=False:
//   v = (v + x_t) - v*0.5 ; s = (v>=1) ; out=s ; v = s?0:v
// Pure streaming: 268MB read + 268MB write, T=4 carried in registers.
// R3: front-batch all 4 loads (MLP=4/warp) + streaming cache hints
// (__ldcs/__stcs — use-once data, keep L2 out of the way).

__device__ __forceinline__ float4 lif_step(float4 xt, float4& v) {
    // exact reference order: v = (v + x) - v*0.5, FMA contraction blocked
    float nx = __fadd_rn(__fadd_rn(v.x, xt.x), -__fmul_rn(v.x, 0.5f));
    float ny = __fadd_rn(__fadd_rn(v.y, xt.y), -__fmul_rn(v.y, 0.5f));
    float nz = __fadd_rn(__fadd_rn(v.z, xt.z), -__fmul_rn(v.z, 0.5f));
    float nw = __fadd_rn(__fadd_rn(v.w, xt.w), -__fmul_rn(v.w, 0.5f));
    float4 s;
    s.x = (nx >= 1.0f) ? 1.0f : 0.0f;
    s.y = (ny >= 1.0f) ? 1.0f : 0.0f;
    s.z = (nz >= 1.0f) ? 1.0f : 0.0f;
    s.w = (nw >= 1.0f) ? 1.0f : 0.0f;
    v.x = (s.x != 0.0f) ? 0.0f : nx;
    v.y = (s.y != 0.0f) ? 0.0f : ny;
    v.z = (s.z != 0.0f) ? 0.0f : nz;
    v.w = (s.w != 0.0f) ? 0.0f : nw;
    return s;
}

__global__ void __launch_bounds__(256)
lif_kernel(const float4* __restrict__ x, float4* __restrict__ out, int n4) {
    int i = blockIdx.x * blockDim.x + threadIdx.x;
    if (i >= n4) return;

    const size_t n = (size_t)n4;

    // Front-batch all 4 independent loads: 4 LDG.128 in flight per thread.
    float4 x0 = __ldcs(&x[i]);
    float4 x1 = __ldcs(&x[n + i]);
    float4 x2 = __ldcs(&x[2 * n + i]);
    float4 x3 = __ldcs(&x[3 * n + i]);

    float4 v = make_float4(0.f, 0.f, 0.f, 0.f);

    float4 s0 = lif_step(x0, v);
    __stcs(&out[i], s0);
    float4 s1 = lif_step(x1, v);
    __stcs(&out[n + i], s1);
    float4 s2 = lif_step(x2, v);
    __stcs(&out[2 * n + i], s2);
    float4 s3 = lif_step(x3, v);
    __stcs(&out[3 * n + i], s3);
}

extern "C" void kernel_launch(void* const* d_in, const int* in_sizes, int n_in,
                              void* d_out, int out_size) {
    const float* x = (const float*)d_in[0];
    float* out = (float*)d_out;

    const int T = 4;
    int n_total = in_sizes[0];          // 67,108,864
    int n_per_step = n_total / T;       // 16,777,216
    int n4 = n_per_step / 4;            // 4,194,304 float4 lanes

    int threads = 256;
    int blocks = (n4 + threads - 1) / threads;
    lif_kernel<<<blocks, threads>>>((const float4*)x, (float4*)out, n4);
}